// round 9
// baseline (speedup 1.0000x reference)
#include <cuda_runtime.h>
#include <cuda_bf16.h>
#include <cstddef>
#include <cstdint>

#define D 128
#define MAX_NODES 50000
#define MAX_EDGES 800000

typedef unsigned int u32;

// Static device scratch (no allocations allowed).
__device__ float g_h[(size_t)MAX_NODES * D];     // layer-0 output
__device__ int   g_degi[MAX_NODES];
__device__ int   g_off[MAX_NODES];
__device__ int   g_cur[MAX_NODES];
__device__ int   g_ssrc[MAX_EDGES];
// Pre-split packed weights: [layer][plane hi/lo][kp][n], u32 = bf16x2(k=2kp,k=2kp+1).
__device__ u32 g_Bp[2][2][128][128];

// ---------------------------------------------------------------------------
// Weight conversion (+ zero degree counters, which count_deg needs next).
// grid = 256 (layer*128 + kp), block = 128 (n).
// ---------------------------------------------------------------------------
__global__ void convert_w_zero_kernel(const float* __restrict__ W0l,
                                      const float* __restrict__ W0r,
                                      const float* __restrict__ W1l,
                                      const float* __restrict__ W1r,
                                      int M) {
    int kp = blockIdx.x & 127;
    int layer = blockIdx.x >> 7;
    int n = threadIdx.x;
    int k0 = 2 * kp;
    const float* W = layer ? (k0 < D ? W1l : W1r) : (k0 < D ? W0l : W0r);
    float v0 = W[(size_t)(k0 & (D - 1)) * D + n];
    float v1 = W[(size_t)((k0 + 1) & (D - 1)) * D + n];
    __nv_bfloat162 h2 = __floats2bfloat162_rn(v0, v1);
    float hx = __bfloat162float(__low2bfloat16(h2));
    float hy = __bfloat162float(__high2bfloat16(h2));
    __nv_bfloat162 l2 = __floats2bfloat162_rn(v0 - hx, v1 - hy);
    g_Bp[layer][0][kp][n] = *reinterpret_cast<u32*>(&h2);
    g_Bp[layer][1][kp][n] = *reinterpret_cast<u32*>(&l2);

    // zero g_degi (32768 threads cover 50000 in 2 strides)
    int idx = blockIdx.x * 128 + n;
    if (idx < M) g_degi[idx] = 0;
    idx += 32768;
    if (idx < M) g_degi[idx] = 0;
}

__global__ void count_deg_kernel(const int* __restrict__ dst, int E) {
    int e = blockIdx.x * blockDim.x + threadIdx.x;
    if (e < E) atomicAdd(&g_degi[dst[e]], 1);
}

// Single-block scan: per-thread serial chunk + block scan; seeds g_off/g_cur.
#define SCAN_THREADS 1024
__global__ void scan_kernel(int n) {
    __shared__ int sums[SCAN_THREADS];
    int t = threadIdx.x;
    int per = (n + SCAN_THREADS - 1) / SCAN_THREADS;
    int beg = t * per;
    int end = beg + per; if (end > n) end = n;
    int s = 0;
    for (int i = beg; i < end; ++i) s += g_degi[i];
    sums[t] = s;
    __syncthreads();
    for (int ofs = 1; ofs < SCAN_THREADS; ofs <<= 1) {
        int v = (t >= ofs) ? sums[t - ofs] : 0;
        __syncthreads();
        sums[t] += v;
        __syncthreads();
    }
    int run = (t == 0) ? 0 : sums[t - 1];
    for (int i = beg; i < end; ++i) {
        g_off[i] = run;
        g_cur[i] = run;
        run += g_degi[i];
    }
}

__global__ void fill_csr_kernel(const int* __restrict__ src,
                                const int* __restrict__ dst, int E) {
    int e = blockIdx.x * blockDim.x + threadIdx.x;
    if (e < E) {
        int p = atomicAdd(&g_cur[dst[e]], 1);
        g_ssrc[p] = src[e];
    }
}

// ---------------------------------------------------------------------------
// Fused gather + SAGE GEMM (3xBF16 mma.sync.m16n8k16), BM=64 x BN=128 tiles.
//   phase 0: A = mean-gather of H over CSR neighbors, B = Wl
//   phase 1: A = H rows (skip path),                  B = Wr
//   out = A0@Wl + A1@Wr + mask(deg>0).*bias (+ReLU).
// PHASE-PARITY DESYNC: odd CTAs run phase 1 first, so at any instant ~half
// the resident CTAs are in the L2-bound gather and half in tensor MMAs.
// ---------------------------------------------------------------------------
#define MMA_BF16(c, a, b)                                                      \
    asm volatile(                                                              \
        "mma.sync.aligned.m16n8k16.row.col.f32.bf16.bf16.f32 "                 \
        "{%0,%1,%2,%3},{%4,%5,%6,%7},{%8,%9},{%0,%1,%2,%3};"                   \
        : "+f"((c)[0]), "+f"((c)[1]), "+f"((c)[2]), "+f"((c)[3])               \
        : "r"((a)[0]), "r"((a)[1]), "r"((a)[2]), "r"((a)[3]),                  \
          "r"((b)[0]), "r"((b)[1]))

#define AFS 68          // full-K A stride: 64 packed words + 4 pad
#define BS_STRIDE 136   // B chunk stride: 128 packed cols + 8 pad
#define SMEM_WORDS (2 * 64 * AFS + 2 * 16 * BS_STRIDE)
#define SMEM_BYTES (SMEM_WORDS * 4)

__device__ __forceinline__ void split2(float x, float y, u32& hi, u32& lo) {
    __nv_bfloat162 h2 = __floats2bfloat162_rn(x, y);
    float hx = __bfloat162float(__low2bfloat16(h2));
    float hy = __bfloat162float(__high2bfloat16(h2));
    __nv_bfloat162 l2 = __floats2bfloat162_rn(x - hx, y - hy);
    hi = *reinterpret_cast<u32*>(&h2);
    lo = *reinterpret_cast<u32*>(&l2);
}

template <bool RELU>
__global__ void __launch_bounds__(256, 3)
sage_fused_kernel(const float* __restrict__ H,
                  const u32* __restrict__ Bhi, const u32* __restrict__ Blo,
                  const float* __restrict__ bias, float* __restrict__ out,
                  int M) {
    extern __shared__ u32 sm[];
    u32* As_hi = sm;                             // 64 * AFS
    u32* As_lo = sm + 64 * AFS;
    u32* Bs_hi = sm + 2 * 64 * AFS;              // 16 * BS_STRIDE
    u32* Bs_lo = sm + 2 * 64 * AFS + 16 * BS_STRIDE;

    const int tid = threadIdx.x;
    const int warp = tid >> 5;
    const int lane = tid & 31;
    const int gid = lane >> 2;
    const int tig = lane & 3;
    const int wm = (warp >> 2) * 32;
    const int wn = (warp & 3) * 32;
    const int block_row = blockIdx.x * 64;
    const int par = blockIdx.x & 1;     // phase order: even=gather first

    const int bkp = tid >> 4;            // B staging: packed-k row 0..15
    const int bcn = (tid & 15) * 8;      //           8 cols per thread

    float acc[2][4][4];
#pragma unroll
    for (int i = 0; i < 2; ++i)
#pragma unroll
        for (int j = 0; j < 4; ++j)
#pragma unroll
            for (int r = 0; r < 4; ++r) acc[i][j][r] = 0.0f;

#pragma unroll 1
    for (int pp = 0; pp < 2; ++pp) {
        const int phase = pp ^ par;
        if (pp == 1) __syncthreads();   // prior phase's A-frag reads done

        if (phase == 0) {
            // ---- gather: warp w produces A rows w*8 .. w*8+7 (mean of nbrs)
            for (int j = 0; j < 8; ++j) {
                int r = warp * 8 + j;
                int row = block_row + r;
                float4 a0 = make_float4(0.f, 0.f, 0.f, 0.f);
                float4 a1 = a0, a2 = a0, a3 = a0;
                if (row < M) {
                    int beg = g_off[row];
                    int dg = g_degi[row];
                    int i = 0;
                    for (; i + 4 <= dg; i += 4) {
                        int s0 = g_ssrc[beg + i];
                        int s1 = g_ssrc[beg + i + 1];
                        int s2 = g_ssrc[beg + i + 2];
                        int s3 = g_ssrc[beg + i + 3];
                        float4 v0 = __ldg(reinterpret_cast<const float4*>(H + (size_t)s0 * D) + lane);
                        float4 v1 = __ldg(reinterpret_cast<const float4*>(H + (size_t)s1 * D) + lane);
                        float4 v2 = __ldg(reinterpret_cast<const float4*>(H + (size_t)s2 * D) + lane);
                        float4 v3 = __ldg(reinterpret_cast<const float4*>(H + (size_t)s3 * D) + lane);
                        a0.x += v0.x; a0.y += v0.y; a0.z += v0.z; a0.w += v0.w;
                        a1.x += v1.x; a1.y += v1.y; a1.z += v1.z; a1.w += v1.w;
                        a2.x += v2.x; a2.y += v2.y; a2.z += v2.z; a2.w += v2.w;
                        a3.x += v3.x; a3.y += v3.y; a3.z += v3.z; a3.w += v3.w;
                    }
                    for (; i < dg; ++i) {
                        int s = g_ssrc[beg + i];
                        float4 v = __ldg(reinterpret_cast<const float4*>(H + (size_t)s * D) + lane);
                        a0.x += v.x; a0.y += v.y; a0.z += v.z; a0.w += v.w;
                    }
                    float inv = (dg > 0) ? 1.0f / (float)dg : 0.0f;
                    a0.x = (a0.x + a1.x + a2.x + a3.x) * inv;
                    a0.y = (a0.y + a1.y + a2.y + a3.y) * inv;
                    a0.z = (a0.z + a1.z + a2.z + a3.z) * inv;
                    a0.w = (a0.w + a1.w + a2.w + a3.w) * inv;
                }
                u32 h0, l0, h1, l1;
                split2(a0.x, a0.y, h0, l0);
                split2(a0.z, a0.w, h1, l1);
                int o = r * AFS + lane * 2;
                As_hi[o] = h0; As_hi[o + 1] = h1;
                As_lo[o] = l0; As_lo[o + 1] = l1;
            }
        } else {
            // ---- skip path: A = H rows
            for (int j = 0; j < 8; ++j) {
                int r = warp * 8 + j;
                int row = block_row + r;
                float4 v = make_float4(0.f, 0.f, 0.f, 0.f);
                if (row < M)
                    v = __ldg(reinterpret_cast<const float4*>(H + (size_t)row * D) + lane);
                u32 h0, l0, h1, l1;
                split2(v.x, v.y, h0, l0);
                split2(v.z, v.w, h1, l1);
                int o = r * AFS + lane * 2;
                As_hi[o] = h0; As_hi[o + 1] = h1;
                As_lo[o] = l0; As_lo[o + 1] = l1;
            }
        }
        const int kpbase = phase * 64;

#pragma unroll 1
        for (int k0 = 0; k0 < D; k0 += 32) {
            const int kc = k0 >> 1;   // packed-word base (0,16,32,48)
            const u32* bsh = Bhi + (size_t)(kpbase + kc + bkp) * 128 + bcn;
            const u32* bsl = Blo + (size_t)(kpbase + kc + bkp) * 128 + bcn;
            uint4 bh0 = __ldg(reinterpret_cast<const uint4*>(bsh));
            uint4 bh1 = __ldg(reinterpret_cast<const uint4*>(bsh + 4));
            uint4 bl0 = __ldg(reinterpret_cast<const uint4*>(bsl));
            uint4 bl1 = __ldg(reinterpret_cast<const uint4*>(bsl + 4));

            __syncthreads();   // prev chunk's Bs reads done; A stores visible
            {
                u32 o = bkp * BS_STRIDE + bcn;
                *reinterpret_cast<uint4*>(&Bs_hi[o]) = bh0;
                *reinterpret_cast<uint4*>(&Bs_hi[o + 4]) = bh1;
                *reinterpret_cast<uint4*>(&Bs_lo[o]) = bl0;
                *reinterpret_cast<uint4*>(&Bs_lo[o + 4]) = bl1;
            }
            __syncthreads();

#pragma unroll
            for (int ks2 = 0; ks2 < 16; ks2 += 8) {
                u32 bh[4][2], bl[4][2];
#pragma unroll
                for (int nt = 0; nt < 4; ++nt) {
                    int nc = wn + nt * 8 + gid;
                    bh[nt][0] = Bs_hi[(ks2 + tig) * BS_STRIDE + nc];
                    bh[nt][1] = Bs_hi[(ks2 + tig + 4) * BS_STRIDE + nc];
                    bl[nt][0] = Bs_lo[(ks2 + tig) * BS_STRIDE + nc];
                    bl[nt][1] = Bs_lo[(ks2 + tig + 4) * BS_STRIDE + nc];
                }
#pragma unroll
                for (int mt = 0; mt < 2; ++mt) {
                    int rr0 = (wm + mt * 16 + gid) * AFS + kc;
                    int rr8 = rr0 + 8 * AFS;
                    u32 ah[4], al[4];
                    ah[0] = As_hi[rr0 + ks2 + tig];
                    ah[1] = As_hi[rr8 + ks2 + tig];
                    ah[2] = As_hi[rr0 + ks2 + tig + 4];
                    ah[3] = As_hi[rr8 + ks2 + tig + 4];
                    al[0] = As_lo[rr0 + ks2 + tig];
                    al[1] = As_lo[rr8 + ks2 + tig];
                    al[2] = As_lo[rr0 + ks2 + tig + 4];
                    al[3] = As_lo[rr8 + ks2 + tig + 4];
#pragma unroll
                    for (int nt = 0; nt < 4; ++nt) {
                        MMA_BF16(acc[mt][nt], ah, bh[nt]);
                        MMA_BF16(acc[mt][nt], ah, bl[nt]);
                        MMA_BF16(acc[mt][nt], al, bh[nt]);
                    }
                }
            }
        }
    }

    // Epilogue: + mask(deg>0)*bias, optional ReLU, float2 stores.
#pragma unroll
    for (int mt = 0; mt < 2; ++mt) {
#pragma unroll
        for (int nt = 0; nt < 4; ++nt) {
            int row0 = block_row + wm + mt * 16 + gid;
            int row1 = row0 + 8;
            int col = wn + nt * 8 + tig * 2;
            float b0v = bias[col];
            float b1v = bias[col + 1];
            if (row0 < M) {
                float m0 = (g_degi[row0] > 0) ? 1.0f : 0.0f;
                float x0 = acc[mt][nt][0] + m0 * b0v;
                float x1 = acc[mt][nt][1] + m0 * b1v;
                if (RELU) { x0 = fmaxf(x0, 0.0f); x1 = fmaxf(x1, 0.0f); }
                *reinterpret_cast<float2*>(out + (size_t)row0 * D + col) = make_float2(x0, x1);
            }
            if (row1 < M) {
                float m1 = (g_degi[row1] > 0) ? 1.0f : 0.0f;
                float x2 = acc[mt][nt][2] + m1 * b0v;
                float x3 = acc[mt][nt][3] + m1 * b1v;
                if (RELU) { x2 = fmaxf(x2, 0.0f); x3 = fmaxf(x3, 0.0f); }
                *reinterpret_cast<float2*>(out + (size_t)row1 * D + col) = make_float2(x2, x3);
            }
        }
    }
}

// ---------------------------------------------------------------------------
// Launch sequence (graph-capturable; all on default stream). 6 launches.
// ---------------------------------------------------------------------------
extern "C" void kernel_launch(void* const* d_in, const int* in_sizes, int n_in,
                              void* d_out, int out_size) {
    const float* x   = (const float*)d_in[0];
    const int*   ei  = (const int*)d_in[1];
    const float* W0l = (const float*)d_in[2];
    const float* b0l = (const float*)d_in[3];
    const float* W0r = (const float*)d_in[4];
    const float* W1l = (const float*)d_in[5];
    const float* b1l = (const float*)d_in[6];
    const float* W1r = (const float*)d_in[7];
    float* out = (float*)d_out;

    const int E = in_sizes[1] / 2;
    const int M = in_sizes[0] / D;
    const int* src = ei;
    const int* dst = ei + E;

    float* h_ptr = nullptr;
    u32* bp_ptr = nullptr;
    cudaGetSymbolAddress((void**)&h_ptr, g_h);
    cudaGetSymbolAddress((void**)&bp_ptr, g_Bp);

    cudaFuncSetAttribute(sage_fused_kernel<true>,
                         cudaFuncAttributeMaxDynamicSharedMemorySize, SMEM_BYTES);
    cudaFuncSetAttribute(sage_fused_kernel<false>,
                         cudaFuncAttributeMaxDynamicSharedMemorySize, SMEM_BYTES);

    const int eb = (E + 255) / 256;
    const int gemmb = (M + 63) / 64;
    const size_t plane = (size_t)128 * 128;

    // Setup: weights (+zero deg) -> count -> scan -> fill
    convert_w_zero_kernel<<<256, 128>>>(W0l, W0r, W1l, W1r, M);
    count_deg_kernel<<<eb, 256>>>(dst, E);
    scan_kernel<<<1, SCAN_THREADS>>>(M);
    fill_csr_kernel<<<eb, 256>>>(src, dst, E);

    // Layer 0: fused gather + GEMM (+ReLU)
    sage_fused_kernel<true><<<gemmb, 256, SMEM_BYTES>>>(
        x, bp_ptr, bp_ptr + plane, b0l, h_ptr, M);

    // Layer 1: fused gather + GEMM
    sage_fused_kernel<false><<<gemmb, 256, SMEM_BYTES>>>(
        h_ptr, bp_ptr + 2 * plane, bp_ptr + 3 * plane, b1l, out, M);
}

// round 10
// speedup vs baseline: 1.5279x; 1.5279x over previous
#include <cuda_runtime.h>
#include <cuda_bf16.h>
#include <cstddef>
#include <cstdint>

#define D 128
#define MAX_NODES 50000
#define MAX_EDGES 800000

typedef unsigned int u32;

// Static device scratch (no allocations allowed).
__device__ float g_h[(size_t)MAX_NODES * D];     // layer-0 output
__device__ int   g_degi[MAX_NODES];
__device__ int   g_off[MAX_NODES];
__device__ int   g_cur[MAX_NODES];
__device__ int   g_ssrc[MAX_EDGES];
__device__ int   g_part[64];
// Pre-split packed weights: [layer][plane hi/lo][kp][n], u32 = bf16x2(k=2kp,k=2kp+1).
__device__ u32 g_Bp[2][2][128][128];

// ---------------------------------------------------------------------------
// Weight conversion + zero g_degi (runs before count_deg; saves one launch).
// grid = 256 (layer*128 + kp), block = 128 (n).
// ---------------------------------------------------------------------------
__global__ void convert_w_zero_kernel(const float* __restrict__ W0l,
                                      const float* __restrict__ W0r,
                                      const float* __restrict__ W1l,
                                      const float* __restrict__ W1r,
                                      int M) {
    int kp = blockIdx.x & 127;
    int layer = blockIdx.x >> 7;
    int n = threadIdx.x;
    int k0 = 2 * kp;
    const float* W = layer ? (k0 < D ? W1l : W1r) : (k0 < D ? W0l : W0r);
    float v0 = W[(size_t)(k0 & (D - 1)) * D + n];
    float v1 = W[(size_t)((k0 + 1) & (D - 1)) * D + n];
    __nv_bfloat162 h2 = __floats2bfloat162_rn(v0, v1);
    float hx = __bfloat162float(__low2bfloat16(h2));
    float hy = __bfloat162float(__high2bfloat16(h2));
    __nv_bfloat162 l2 = __floats2bfloat162_rn(v0 - hx, v1 - hy);
    g_Bp[layer][0][kp][n] = *reinterpret_cast<u32*>(&h2);
    g_Bp[layer][1][kp][n] = *reinterpret_cast<u32*>(&l2);

    int idx = blockIdx.x * 128 + n;          // 32768 threads, 2 strides cover 50k
    if (idx < M) g_degi[idx] = 0;
    idx += 32768;
    if (idx < M) g_degi[idx] = 0;
}

__global__ void count_deg_kernel(const int* __restrict__ dst, int E) {
    int e = blockIdx.x * blockDim.x + threadIdx.x;
    if (e < E) atomicAdd(&g_degi[dst[e]], 1);
}

#define SCAN_BLK 1024
__global__ void scan_part_kernel(int n) {
    __shared__ int red[SCAN_BLK];
    int tid = threadIdx.x;
    int i = blockIdx.x * SCAN_BLK + tid;
    red[tid] = (i < n) ? g_degi[i] : 0;
    __syncthreads();
#pragma unroll
    for (int ofs = SCAN_BLK / 2; ofs > 0; ofs >>= 1) {
        if (tid < ofs) red[tid] += red[tid + ofs];
        __syncthreads();
    }
    if (tid == 0) g_part[blockIdx.x] = red[0];
}

__global__ void scan_base_kernel(int nb) {
    if (threadIdx.x == 0) {
        int run = 0;
        for (int i = 0; i < nb; ++i) { int t = g_part[i]; g_part[i] = run; run += t; }
    }
}

__global__ void scan_write_kernel(int n) {
    __shared__ int s[SCAN_BLK];
    int tid = threadIdx.x;
    int i = blockIdx.x * SCAN_BLK + tid;
    int v = (i < n) ? g_degi[i] : 0;
    s[tid] = v;
    __syncthreads();
    for (int ofs = 1; ofs < SCAN_BLK; ofs <<= 1) {
        int t = (tid >= ofs) ? s[tid - ofs] : 0;
        __syncthreads();
        s[tid] += t;
        __syncthreads();
    }
    int excl = s[tid] - v + g_part[blockIdx.x];
    if (i < n) { g_off[i] = excl; g_cur[i] = excl; }
}

__global__ void fill_csr_kernel(const int* __restrict__ src,
                                const int* __restrict__ dst, int E) {
    int e = blockIdx.x * blockDim.x + threadIdx.x;
    if (e < E) {
        int p = atomicAdd(&g_cur[dst[e]], 1);
        g_ssrc[p] = src[e];
    }
}

// ---------------------------------------------------------------------------
// Fused gather + SAGE GEMM (3xBF16 mma.sync.m16n8k16), BM=64 x BN=128 tiles.
//   Phase 0: A = mean-gather of H over CSR neighbors (all warps gather —
//            full-SM participation is required to saturate L2 BW; R9 showed
//            desynchronizing phases starves the gather of MLP).
//   Phase 1: A = H rows (skip path).
//   out = A0@Wl + A1@Wr + mask(deg>0).*bias (+ReLU).
// ---------------------------------------------------------------------------
#define MMA_BF16(c, a, b)                                                      \
    asm volatile(                                                              \
        "mma.sync.aligned.m16n8k16.row.col.f32.bf16.bf16.f32 "                 \
        "{%0,%1,%2,%3},{%4,%5,%6,%7},{%8,%9},{%0,%1,%2,%3};"                   \
        : "+f"((c)[0]), "+f"((c)[1]), "+f"((c)[2]), "+f"((c)[3])               \
        : "r"((a)[0]), "r"((a)[1]), "r"((a)[2]), "r"((a)[3]),                  \
          "r"((b)[0]), "r"((b)[1]))

#define AFS 68          // full-K A stride: 64 packed words + 4 pad
#define BS_STRIDE 136   // B chunk stride: 128 packed cols + 8 pad
#define SMEM_WORDS (2 * 64 * AFS + 2 * 16 * BS_STRIDE)
#define SMEM_BYTES (SMEM_WORDS * 4)

__device__ __forceinline__ void split2(float x, float y, u32& hi, u32& lo) {
    __nv_bfloat162 h2 = __floats2bfloat162_rn(x, y);
    float hx = __bfloat162float(__low2bfloat16(h2));
    float hy = __bfloat162float(__high2bfloat16(h2));
    __nv_bfloat162 l2 = __floats2bfloat162_rn(x - hx, y - hy);
    hi = *reinterpret_cast<u32*>(&h2);
    lo = *reinterpret_cast<u32*>(&l2);
}

template <bool RELU>
__global__ void __launch_bounds__(256, 3)
sage_fused_kernel(const float* __restrict__ H,
                  const u32* __restrict__ Bhi, const u32* __restrict__ Blo,
                  const float* __restrict__ bias, float* __restrict__ out,
                  int M) {
    extern __shared__ u32 sm[];
    u32* As_hi = sm;                             // 64 * AFS
    u32* As_lo = sm + 64 * AFS;
    u32* Bs_hi = sm + 2 * 64 * AFS;              // 16 * BS_STRIDE
    u32* Bs_lo = sm + 2 * 64 * AFS + 16 * BS_STRIDE;

    const int tid = threadIdx.x;
    const int warp = tid >> 5;
    const int lane = tid & 31;
    const int gid = lane >> 2;
    const int tig = lane & 3;
    const int wm = (warp >> 2) * 32;
    const int wn = (warp & 3) * 32;
    const int block_row = blockIdx.x * 64;

    const int bkp = tid >> 4;            // B staging: packed-k row 0..15
    const int bcn = (tid & 15) * 8;      //           8 cols per thread

    // ---- gather phase: warp w produces A rows w*8 .. w*8+7 (mean of nbrs) ----
    for (int j = 0; j < 8; ++j) {
        int r = warp * 8 + j;
        int row = block_row + r;
        float4 a0 = make_float4(0.f, 0.f, 0.f, 0.f);
        float4 a1 = a0, a2 = a0, a3 = a0;
        if (row < M) {
            int beg = g_off[row];
            int dg = g_degi[row];
            int i = 0;
            for (; i + 4 <= dg; i += 4) {
                int s0 = g_ssrc[beg + i];
                int s1 = g_ssrc[beg + i + 1];
                int s2 = g_ssrc[beg + i + 2];
                int s3 = g_ssrc[beg + i + 3];
                float4 v0 = __ldg(reinterpret_cast<const float4*>(H + (size_t)s0 * D) + lane);
                float4 v1 = __ldg(reinterpret_cast<const float4*>(H + (size_t)s1 * D) + lane);
                float4 v2 = __ldg(reinterpret_cast<const float4*>(H + (size_t)s2 * D) + lane);
                float4 v3 = __ldg(reinterpret_cast<const float4*>(H + (size_t)s3 * D) + lane);
                a0.x += v0.x; a0.y += v0.y; a0.z += v0.z; a0.w += v0.w;
                a1.x += v1.x; a1.y += v1.y; a1.z += v1.z; a1.w += v1.w;
                a2.x += v2.x; a2.y += v2.y; a2.z += v2.z; a2.w += v2.w;
                a3.x += v3.x; a3.y += v3.y; a3.z += v3.z; a3.w += v3.w;
            }
            for (; i < dg; ++i) {
                int s = g_ssrc[beg + i];
                float4 v = __ldg(reinterpret_cast<const float4*>(H + (size_t)s * D) + lane);
                a0.x += v.x; a0.y += v.y; a0.z += v.z; a0.w += v.w;
            }
            float inv = (dg > 0) ? 1.0f / (float)dg : 0.0f;
            a0.x = (a0.x + a1.x + a2.x + a3.x) * inv;
            a0.y = (a0.y + a1.y + a2.y + a3.y) * inv;
            a0.z = (a0.z + a1.z + a2.z + a3.z) * inv;
            a0.w = (a0.w + a1.w + a2.w + a3.w) * inv;
        }
        u32 h0, l0, h1, l1;
        split2(a0.x, a0.y, h0, l0);
        split2(a0.z, a0.w, h1, l1);
        int o = r * AFS + lane * 2;
        As_hi[o] = h0; As_hi[o + 1] = h1;
        As_lo[o] = l0; As_lo[o + 1] = l1;
    }

    float acc[2][4][4];
#pragma unroll
    for (int i = 0; i < 2; ++i)
#pragma unroll
        for (int j = 0; j < 4; ++j)
#pragma unroll
            for (int r = 0; r < 4; ++r) acc[i][j][r] = 0.0f;

#pragma unroll 1
    for (int phase = 0; phase < 2; ++phase) {
        if (phase == 1) {
            __syncthreads();   // all phase-0 A-frag reads done before overwrite
            // restage A = H rows (skip path)
            for (int j = 0; j < 8; ++j) {
                int r = warp * 8 + j;
                int row = block_row + r;
                float4 v = make_float4(0.f, 0.f, 0.f, 0.f);
                if (row < M)
                    v = __ldg(reinterpret_cast<const float4*>(H + (size_t)row * D) + lane);
                u32 h0, l0, h1, l1;
                split2(v.x, v.y, h0, l0);
                split2(v.z, v.w, h1, l1);
                int o = r * AFS + lane * 2;
                As_hi[o] = h0; As_hi[o + 1] = h1;
                As_lo[o] = l0; As_lo[o + 1] = l1;
            }
        }
        const int kpbase = phase * 64;

#pragma unroll 1
        for (int k0 = 0; k0 < D; k0 += 32) {
            const int kc = k0 >> 1;   // packed-word base of this chunk (0,16,32,48)
            const u32* bsh = Bhi + (size_t)(kpbase + kc + bkp) * 128 + bcn;
            const u32* bsl = Blo + (size_t)(kpbase + kc + bkp) * 128 + bcn;
            uint4 bh0 = __ldg(reinterpret_cast<const uint4*>(bsh));
            uint4 bh1 = __ldg(reinterpret_cast<const uint4*>(bsh + 4));
            uint4 bl0 = __ldg(reinterpret_cast<const uint4*>(bsl));
            uint4 bl1 = __ldg(reinterpret_cast<const uint4*>(bsl + 4));

            __syncthreads();   // previous chunk's Bs reads done; A stores visible
            {
                u32 o = bkp * BS_STRIDE + bcn;
                *reinterpret_cast<uint4*>(&Bs_hi[o]) = bh0;
                *reinterpret_cast<uint4*>(&Bs_hi[o + 4]) = bh1;
                *reinterpret_cast<uint4*>(&Bs_lo[o]) = bl0;
                *reinterpret_cast<uint4*>(&Bs_lo[o + 4]) = bl1;
            }
            __syncthreads();

#pragma unroll
            for (int ks2 = 0; ks2 < 16; ks2 += 8) {
                u32 bh[4][2], bl[4][2];
#pragma unroll
                for (int nt = 0; nt < 4; ++nt) {
                    int nc = wn + nt * 8 + gid;
                    bh[nt][0] = Bs_hi[(ks2 + tig) * BS_STRIDE + nc];
                    bh[nt][1] = Bs_hi[(ks2 + tig + 4) * BS_STRIDE + nc];
                    bl[nt][0] = Bs_lo[(ks2 + tig) * BS_STRIDE + nc];
                    bl[nt][1] = Bs_lo[(ks2 + tig + 4) * BS_STRIDE + nc];
                }
#pragma unroll
                for (int mt = 0; mt < 2; ++mt) {
                    int rr0 = (wm + mt * 16 + gid) * AFS + kc;
                    int rr8 = rr0 + 8 * AFS;
                    u32 ah[4], al[4];
                    ah[0] = As_hi[rr0 + ks2 + tig];
                    ah[1] = As_hi[rr8 + ks2 + tig];
                    ah[2] = As_hi[rr0 + ks2 + tig + 4];
                    ah[3] = As_hi[rr8 + ks2 + tig + 4];
                    al[0] = As_lo[rr0 + ks2 + tig];
                    al[1] = As_lo[rr8 + ks2 + tig];
                    al[2] = As_lo[rr0 + ks2 + tig + 4];
                    al[3] = As_lo[rr8 + ks2 + tig + 4];
#pragma unroll
                    for (int nt = 0; nt < 4; ++nt) {
                        MMA_BF16(acc[mt][nt], ah, bh[nt]);
                        MMA_BF16(acc[mt][nt], ah, bl[nt]);
                        MMA_BF16(acc[mt][nt], al, bh[nt]);
                    }
                }
            }
        }
    }

    // Epilogue: + mask(deg>0)*bias, optional ReLU, float2 stores.
#pragma unroll
    for (int mt = 0; mt < 2; ++mt) {
#pragma unroll
        for (int nt = 0; nt < 4; ++nt) {
            int row0 = block_row + wm + mt * 16 + gid;
            int row1 = row0 + 8;
            int col = wn + nt * 8 + tig * 2;
            float b0v = bias[col];
            float b1v = bias[col + 1];
            if (row0 < M) {
                float m0 = (g_degi[row0] > 0) ? 1.0f : 0.0f;
                float x0 = acc[mt][nt][0] + m0 * b0v;
                float x1 = acc[mt][nt][1] + m0 * b1v;
                if (RELU) { x0 = fmaxf(x0, 0.0f); x1 = fmaxf(x1, 0.0f); }
                *reinterpret_cast<float2*>(out + (size_t)row0 * D + col) = make_float2(x0, x1);
            }
            if (row1 < M) {
                float m1 = (g_degi[row1] > 0) ? 1.0f : 0.0f;
                float x2 = acc[mt][nt][2] + m1 * b0v;
                float x3 = acc[mt][nt][3] + m1 * b1v;
                if (RELU) { x2 = fmaxf(x2, 0.0f); x3 = fmaxf(x3, 0.0f); }
                *reinterpret_cast<float2*>(out + (size_t)row1 * D + col) = make_float2(x2, x3);
            }
        }
    }
}

// ---------------------------------------------------------------------------
// Launch sequence (graph-capturable; all on default stream). 8 launches.
// ---------------------------------------------------------------------------
extern "C" void kernel_launch(void* const* d_in, const int* in_sizes, int n_in,
                              void* d_out, int out_size) {
    const float* x   = (const float*)d_in[0];
    const int*   ei  = (const int*)d_in[1];
    const float* W0l = (const float*)d_in[2];
    const float* b0l = (const float*)d_in[3];
    const float* W0r = (const float*)d_in[4];
    const float* W1l = (const float*)d_in[5];
    const float* b1l = (const float*)d_in[6];
    const float* W1r = (const float*)d_in[7];
    float* out = (float*)d_out;

    const int E = in_sizes[1] / 2;
    const int M = in_sizes[0] / D;
    const int* src = ei;
    const int* dst = ei + E;

    float* h_ptr = nullptr;
    u32* bp_ptr = nullptr;
    cudaGetSymbolAddress((void**)&h_ptr, g_h);
    cudaGetSymbolAddress((void**)&bp_ptr, g_Bp);

    cudaFuncSetAttribute(sage_fused_kernel<true>,
                         cudaFuncAttributeMaxDynamicSharedMemorySize, SMEM_BYTES);
    cudaFuncSetAttribute(sage_fused_kernel<false>,
                         cudaFuncAttributeMaxDynamicSharedMemorySize, SMEM_BYTES);

    const int eb = (E + 255) / 256;
    const int scanb = (M + SCAN_BLK - 1) / SCAN_BLK;
    const int gemmb = (M + 63) / 64;
    const size_t plane = (size_t)128 * 128;

    // Setup: weights (+zero deg) -> count -> scan -> fill
    convert_w_zero_kernel<<<256, 128>>>(W0l, W0r, W1l, W1r, M);
    count_deg_kernel<<<eb, 256>>>(dst, E);
    scan_part_kernel<<<scanb, SCAN_BLK>>>(M);
    scan_base_kernel<<<1, 32>>>(scanb);
    scan_write_kernel<<<scanb, SCAN_BLK>>>(M);
    fill_csr_kernel<<<eb, 256>>>(src, dst, E);

    // Layer 0: fused gather + GEMM (+ReLU)
    sage_fused_kernel<true><<<gemmb, 256, SMEM_BYTES>>>(
        x, bp_ptr, bp_ptr + plane, b0l, h_ptr, M);

    // Layer 1: fused gather + GEMM
    sage_fused_kernel<false><<<gemmb, 256, SMEM_BYTES>>>(
        h_ptr, bp_ptr + 2 * plane, bp_ptr + 3 * plane, b1l, out, M);
}